// round 8
// baseline (speedup 1.0000x reference)
#include <cuda_runtime.h>
#include <cuda_bf16.h>
#include <cstdint>

// ---------------- problem constants ----------------
#define C_IN   256
#define C_OUT  256
#define HW     4096
#define KTAPS  9
#define KTOT   2304          // tap-major: kord = tap*256 + c
#define MTOT   16384

// ---------------- GEMM tiling ----------------
#define BM 128
#define BN 256
#define BK 64
#define NCHUNK 36            // KTOT/BK
#define NTHREADS 256

#define PITCH 144            // 64 k * 2B + 16B pad (conflict-free)
#define ABUF  (BM * PITCH)   // 18432
#define BBUF  (BN * PITCH)   // 36864
#define STAGE (2 * ABUF + 2 * BBUF)   // 110592
#define GAH 0
#define GAL ABUF
#define GBH (2 * ABUF)
#define GBL (2 * ABUF + BBUF)
#define GSMEM (2 * STAGE)    // 221184

#define CS_PITCH 129

// ---------------- device scratch ----------------
__device__ float    g_xT[4 * HW * C_IN];                  // NHWC, 16MB
__device__ __align__(16) uint16_t g_wBh[C_OUT * KTOT];    // bf16 hi, [o][kord]
__device__ __align__(16) uint16_t g_wBl[C_OUT * KTOT];    // bf16 lo
__device__ __align__(16) uint16_t g_Ah[(size_t)MTOT * KTOT];  // im2col hi
__device__ __align__(16) uint16_t g_Al[(size_t)MTOT * KTOT];  // im2col lo

// ---------------- prep kernels ----------------
__global__ void prep_w(const float* __restrict__ w) {
    int i = blockIdx.x * 256 + threadIdx.x;
    int kord = i % KTOT;
    int o    = i / KTOT;
    int tap  = kord >> 8;
    int c    = kord & 255;
    float v = w[o * KTOT + c * KTAPS + tap];
    __nv_bfloat16 h = __float2bfloat16_rn(v);
    float r = v - __bfloat162float(h);
    __nv_bfloat16 l = __float2bfloat16_rn(r);
    g_wBh[i] = *(uint16_t*)&h;
    g_wBl[i] = *(uint16_t*)&l;
}

__global__ void transpose_x(const float* __restrict__ x) {
    __shared__ float t[32][33];
    const int b   = blockIdx.z;
    const int hw0 = blockIdx.x * 32;
    const int c0  = blockIdx.y * 32;
    const int tx  = threadIdx.x, ty = threadIdx.y;
    #pragma unroll
    for (int i = 0; i < 4; ++i)
        t[ty + i * 8][tx] = x[((b * C_IN + c0 + ty + i * 8) << 12) + hw0 + tx];
    __syncthreads();
    #pragma unroll
    for (int i = 0; i < 4; ++i)
        g_xT[b * (HW * C_IN) + (hw0 + ty + i * 8) * C_IN + c0 + tx] =
            t[tx][ty + i * 8];
}

// ---------------- im2col + bf16 split (no smem, no syncs) ----------------
__global__ __launch_bounds__(256)
void im2col_split(const float* __restrict__ off)
{
    const int tid = threadIdx.x;
    const int pos = tid >> 3;
    const int sub = tid & 7;
    const int m   = blockIdx.x * 32 + pos;
    const int b   = m >> 12;
    const int hw  = m & 4095;
    const int ho  = hw >> 6, wo = hw & 63;
    const char* xTb = (const char*)g_xT + ((size_t)b << 22);
    uint16_t* dAh = g_Ah + (size_t)m * KTOT;
    uint16_t* dAl = g_Al + (size_t)m * KTOT;

    #pragma unroll 1
    for (int tap = 0; tap < KTAPS; ++tap) {
        const float offy = off[((b * 18 + 2 * tap)     << 12) + hw];
        const float offx = off[((b * 18 + 2 * tap + 1) << 12) + hw];
        const float py = (float)(ho - 1 + tap / 3) + offy;
        const float px = (float)(wo - 1 + tap % 3) + offx;
        const float y0f = floorf(py), x0f = floorf(px);
        const int y0 = (int)y0f, x0 = (int)x0f;
        const float fy = py - y0f, fx = px - x0f;
        float w00 = (1.f - fy) * (1.f - fx), w01 = (1.f - fy) * fx;
        float w10 = fy * (1.f - fx),         w11 = fy * fx;
        const bool vy0 = (unsigned)y0 < 64u, vy1 = (unsigned)(y0 + 1) < 64u;
        const bool vx0 = (unsigned)x0 < 64u, vx1 = (unsigned)(x0 + 1) < 64u;
        if (!(vy0 && vx0)) w00 = 0.f;
        if (!(vy0 && vx1)) w01 = 0.f;
        if (!(vy1 && vx0)) w10 = 0.f;
        if (!(vy1 && vx1)) w11 = 0.f;
        const int cy0 = min(max(y0, 0), 63), cy1 = min(max(y0 + 1, 0), 63);
        const int cx0 = min(max(x0, 0), 63), cx1 = min(max(x0 + 1, 0), 63);
        const int o00 = (cy0 * 64 + cx0) << 10, o01 = (cy0 * 64 + cx1) << 10;
        const int o10 = (cy1 * 64 + cx0) << 10, o11 = (cy1 * 64 + cx1) << 10;

        #pragma unroll
        for (int j = 0; j < 8; ++j) {
            const int co = j * 128 + sub * 16;
            const float4 a0 = *(const float4*)(xTb + o00 + co);
            const float4 a1 = *(const float4*)(xTb + o01 + co);
            const float4 a2 = *(const float4*)(xTb + o10 + co);
            const float4 a3 = *(const float4*)(xTb + o11 + co);
            float4 v;
            v.x = w00*a0.x + w01*a1.x + w10*a2.x + w11*a3.x;
            v.y = w00*a0.y + w01*a1.y + w10*a2.y + w11*a3.y;
            v.z = w00*a0.z + w01*a1.z + w10*a2.z + w11*a3.z;
            v.w = w00*a0.w + w01*a1.w + w10*a2.w + w11*a3.w;
            __nv_bfloat162 h0 = __floats2bfloat162_rn(v.x, v.y);
            __nv_bfloat162 h1 = __floats2bfloat162_rn(v.z, v.w);
            __nv_bfloat162 l0 = __floats2bfloat162_rn(
                v.x - __bfloat162float(h0.x), v.y - __bfloat162float(h0.y));
            __nv_bfloat162 l1 = __floats2bfloat162_rn(
                v.z - __bfloat162float(h1.x), v.w - __bfloat162float(h1.y));
            const int ko = tap * 256 + j * 32 + sub * 4;
            *(uint2*)(dAh + ko) = make_uint2(*(uint32_t*)&h0, *(uint32_t*)&h1);
            *(uint2*)(dAl + ko) = make_uint2(*(uint32_t*)&l0, *(uint32_t*)&l1);
        }
    }
}

// ---------------- asm helpers ----------------
__device__ __forceinline__ uint32_t smem_u32(const void* p) {
    uint32_t a;
    asm("{ .reg .u64 t; cvta.to.shared.u64 t, %1; cvt.u32.u64 %0, t; }"
        : "=r"(a) : "l"(p));
    return a;
}
__device__ __forceinline__ void ldsm4(uint32_t* r, uint32_t a) {
    asm volatile("ldmatrix.sync.aligned.m8n8.x4.shared.b16 {%0,%1,%2,%3}, [%4];"
                 : "=r"(r[0]), "=r"(r[1]), "=r"(r[2]), "=r"(r[3]) : "r"(a));
}
__device__ __forceinline__ void hmma(float* d, const uint32_t* a,
                                     uint32_t b0, uint32_t b1) {
    asm volatile(
        "mma.sync.aligned.m16n8k16.row.col.f32.bf16.bf16.f32 "
        "{%0,%1,%2,%3}, {%4,%5,%6,%7}, {%8,%9}, {%0,%1,%2,%3};"
        : "+f"(d[0]), "+f"(d[1]), "+f"(d[2]), "+f"(d[3])
        : "r"(a[0]), "r"(a[1]), "r"(a[2]), "r"(a[3]), "r"(b0), "r"(b1));
}
__device__ __forceinline__ void cpasync16(uint32_t dst, const void* src) {
    asm volatile("cp.async.cg.shared.global [%0], [%1], 16;"
                 :: "r"(dst), "l"(src) : "memory");
}

// ---------------- dense GEMM: warp tile M64 x N64 ----------------
__global__ __launch_bounds__(NTHREADS, 1)
void gemm(const float* __restrict__ bias, float* __restrict__ out)
{
    extern __shared__ char smem[];
    const uint32_t sbase = smem_u32(smem);
    const int tid = threadIdx.x;
    const int wid = tid >> 5;
    const int lid = tid & 31;

    const int mtile = blockIdx.x * BM;
    const int b   = mtile >> 12;
    const int hw0 = mtile & 4095;

    // 8 warps: 2 m-groups x 4 n-groups, warp tile M64 x N64
    const int mrow = (wid & 1) * 64;
    const int ncol = (wid >> 1) * 64;
    const uint32_t aoff = (uint32_t)(lid & 15) * PITCH + (uint32_t)(lid >> 4) * 16;
    const uint32_t boff = (uint32_t)(lid & 7) * PITCH
                        + (uint32_t)((lid >> 3) & 1) * 16
                        + (uint32_t)(lid >> 4) * (8 * PITCH);

    float acc[4][8][4];
    #pragma unroll
    for (int i = 0; i < 4; ++i)
        #pragma unroll
        for (int j = 0; j < 8; ++j)
            #pragma unroll
            for (int k = 0; k < 4; ++k) acc[i][j][k] = 0.f;

    auto fill = [&](int chunk, int st) {
        const int ke = chunk * BK;
        const uint32_t base = sbase + st * STAGE;
        // A hi/lo: 1024 x 16B each -> 4 per thread per split
        #pragma unroll
        for (int i = 0; i < 4; ++i) {
            const int id = tid + (i << 8);
            const int row = id >> 3, s = id & 7;
            const uint32_t d = (uint32_t)(row * PITCH + s * 16);
            const size_t g = (size_t)(mtile + row) * KTOT + ke + s * 8;
            cpasync16(base + GAH + d, g_Ah + g);
            cpasync16(base + GAL + d, g_Al + g);
        }
        // B hi/lo: 2048 x 16B each -> 8 per thread per split
        #pragma unroll
        for (int i = 0; i < 8; ++i) {
            const int id = tid + (i << 8);
            const int n = id >> 3, s = id & 7;
            const uint32_t d = (uint32_t)(n * PITCH + s * 16);
            const size_t g = (size_t)n * KTOT + ke + s * 8;
            cpasync16(base + GBH + d, g_wBh + g);
            cpasync16(base + GBL + d, g_wBl + g);
        }
        asm volatile("cp.async.commit_group;" ::: "memory");
    };

    auto do_mma = [&](int st) {
        const uint32_t base = sbase + st * STAGE;
        const uint32_t sAh = base + GAH + mrow * PITCH + aoff;
        const uint32_t sAl = base + GAL + mrow * PITCH + aoff;
        const uint32_t sBh = base + GBH + ncol * PITCH + boff;
        const uint32_t sBl = base + GBL + ncol * PITCH + boff;
        #pragma unroll
        for (int ks = 0; ks < 4; ++ks) {
            const uint32_t ka = ks * 32;
            // load ALL B frags for this ks first (32 regs), then stream A per-ms
            uint32_t bh4[4][4], bl4[4][4];
            #pragma unroll
            for (int np = 0; np < 4; ++np) {
                ldsm4(bh4[np], sBh + np * (16 * PITCH) + ka);
                ldsm4(bl4[np], sBl + np * (16 * PITCH) + ka);
            }
            #pragma unroll
            for (int ms = 0; ms < 4; ++ms) {
                uint32_t ahf[4], alf[4];
                ldsm4(ahf, sAh + ms * (16 * PITCH) + ka);
                ldsm4(alf, sAl + ms * (16 * PITCH) + ka);
                #pragma unroll
                for (int np = 0; np < 4; ++np) {
                    hmma(acc[ms][np * 2],     ahf, bh4[np][0], bh4[np][1]);
                    hmma(acc[ms][np * 2 + 1], ahf, bh4[np][2], bh4[np][3]);
                    hmma(acc[ms][np * 2],     ahf, bl4[np][0], bl4[np][1]);
                    hmma(acc[ms][np * 2 + 1], ahf, bl4[np][2], bl4[np][3]);
                    hmma(acc[ms][np * 2],     alf, bh4[np][0], bh4[np][1]);
                    hmma(acc[ms][np * 2 + 1], alf, bh4[np][2], bh4[np][3]);
                }
            }
        }
    };

    // ---- 2-stage pipeline ----
    fill(0, 0);
    asm volatile("cp.async.wait_group 0;" ::: "memory");
    __syncthreads();

    #pragma unroll 1
    for (int chunk = 0; chunk < NCHUNK; ++chunk) {
        const int st = chunk & 1;
        if (chunk + 1 < NCHUNK) fill(chunk + 1, st ^ 1);
        do_mma(st);
        asm volatile("cp.async.wait_group 0;" ::: "memory");
        __syncthreads();
    }

    // ---- epilogue: transpose through smem, coalesced stores ----
    float* csf = (float*)smem;
    const int g  = lid >> 2;
    const int t2 = (lid & 3) * 2;
    const int outbase = (b << 20) + hw0;
    #pragma unroll 1
    for (int p = 0; p < 8; ++p) {
        if ((wid >> 1) == (p >> 1)) {
            const int nsb = (p & 1) * 4;
            #pragma unroll
            for (int ns2 = 0; ns2 < 4; ++ns2) {
                const int nl = ns2 * 8 + t2;
                #pragma unroll
                for (int ms = 0; ms < 4; ++ms) {
                    const float* a4 = acc[ms][nsb + ns2];
                    const int m = mrow + ms * 16 + g;
                    csf[nl * CS_PITCH + m]           = a4[0];
                    csf[(nl + 1) * CS_PITCH + m]     = a4[1];
                    csf[nl * CS_PITCH + m + 8]       = a4[2];
                    csf[(nl + 1) * CS_PITCH + m + 8] = a4[3];
                }
            }
        }
        __syncthreads();
        #pragma unroll
        for (int it = 0; it < 16; ++it) {
            const int e = tid + it * NTHREADS;
            const int mm = e & 127;
            const int nn = e >> 7;          // 0..31
            const int n = p * 32 + nn;
            out[outbase + (n << 12) + mm] = csf[nn * CS_PITCH + mm] + __ldg(bias + n);
        }
        __syncthreads();
    }
}

extern "C" void kernel_launch(void* const* d_in, const int* in_sizes, int n_in,
                              void* d_out, int out_size)
{
    const float* x    = (const float*)d_in[0];
    const float* off  = (const float*)d_in[1];
    const float* w    = (const float*)d_in[2];
    const float* bias = (const float*)d_in[3];
    float* out        = (float*)d_out;

    cudaFuncSetAttribute(gemm, cudaFuncAttributeMaxDynamicSharedMemorySize, GSMEM);

    transpose_x<<<dim3(HW / 32, C_IN / 32, 4), dim3(32, 8)>>>(x);
    prep_w<<<(C_OUT * KTOT) / 256, 256>>>(w);
    im2col_split<<<MTOT / 32, 256>>>(off);
    gemm<<<MTOT / BM, NTHREADS, GSMEM>>>(bias, out);
}

// round 11
// speedup vs baseline: 1.1559x; 1.1559x over previous
#include <cuda_runtime.h>
#include <cuda_fp16.h>
#include <cstdint>

// ---------------- problem constants ----------------
#define C_IN   256
#define C_OUT  256
#define HW     4096
#define KTAPS  9
#define KTOT   2304          // tap-major: kord = tap*256 + c
#define MTOT   16384

// ---------------- GEMM tiling ----------------
#define BM 128
#define BN 256
#define BK 64
#define NCHUNK 36            // KTOT/BK
#define NTHREADS 256

#define PITCH 144            // 64 k * 2B + 16B pad (conflict-free)
#define ABUF  (BM * PITCH)   // 18432
#define BBUF  (BN * PITCH)   // 36864
#define STAGE (ABUF + 2 * BBUF)       // 92160
#define GA  0
#define GBH ABUF
#define GBL (ABUF + BBUF)
#define GSMEM (2 * STAGE)    // 184320

#define CS_PITCH 129

// ---------------- device scratch ----------------
__device__ float    g_xT[4 * HW * C_IN];                  // NHWC, 16MB
__device__ __align__(16) uint16_t g_wBh[C_OUT * KTOT];    // fp16 hi, [o][kord]
__device__ __align__(16) uint16_t g_wBl[C_OUT * KTOT];    // fp16 lo (residual)
__device__ __align__(16) uint16_t g_Af[(size_t)MTOT * KTOT];  // im2col fp16

// ---------------- prep kernels ----------------
__global__ void prep_w(const float* __restrict__ w) {
    int i = blockIdx.x * 256 + threadIdx.x;
    int kord = i % KTOT;
    int o    = i / KTOT;
    int tap  = kord >> 8;
    int c    = kord & 255;
    float v = w[o * KTOT + c * KTAPS + tap];
    __half h = __float2half_rn(v);
    float r = v - __half2float(h);
    __half l = __float2half_rn(r);
    g_wBh[i] = *(uint16_t*)&h;
    g_wBl[i] = *(uint16_t*)&l;
}

__global__ void transpose_x(const float* __restrict__ x) {
    __shared__ float t[32][33];
    const int b   = blockIdx.z;
    const int hw0 = blockIdx.x * 32;
    const int c0  = blockIdx.y * 32;
    const int tx  = threadIdx.x, ty = threadIdx.y;
    #pragma unroll
    for (int i = 0; i < 4; ++i)
        t[ty + i * 8][tx] = x[((b * C_IN + c0 + ty + i * 8) << 12) + hw0 + tx];
    __syncthreads();
    #pragma unroll
    for (int i = 0; i < 4; ++i)
        g_xT[b * (HW * C_IN) + (hw0 + ty + i * 8) * C_IN + c0 + tx] =
            t[tx][ty + i * 8];
}

// ---------------- im2col -> single fp16 (no smem, no syncs) ----------------
__global__ __launch_bounds__(256)
void im2col_f16(const float* __restrict__ off)
{
    const int tid = threadIdx.x;
    const int pos = tid >> 3;
    const int sub = tid & 7;
    const int m   = blockIdx.x * 32 + pos;
    const int b   = m >> 12;
    const int hw  = m & 4095;
    const int ho  = hw >> 6, wo = hw & 63;
    const char* xTb = (const char*)g_xT + ((size_t)b << 22);
    uint16_t* dA = g_Af + (size_t)m * KTOT;

    #pragma unroll 1
    for (int tap = 0; tap < KTAPS; ++tap) {
        const float offy = off[((b * 18 + 2 * tap)     << 12) + hw];
        const float offx = off[((b * 18 + 2 * tap + 1) << 12) + hw];
        const float py = (float)(ho - 1 + tap / 3) + offy;
        const float px = (float)(wo - 1 + tap % 3) + offx;
        const float y0f = floorf(py), x0f = floorf(px);
        const int y0 = (int)y0f, x0 = (int)x0f;
        const float fy = py - y0f, fx = px - x0f;
        float w00 = (1.f - fy) * (1.f - fx), w01 = (1.f - fy) * fx;
        float w10 = fy * (1.f - fx),         w11 = fy * fx;
        const bool vy0 = (unsigned)y0 < 64u, vy1 = (unsigned)(y0 + 1) < 64u;
        const bool vx0 = (unsigned)x0 < 64u, vx1 = (unsigned)(x0 + 1) < 64u;
        if (!(vy0 && vx0)) w00 = 0.f;
        if (!(vy0 && vx1)) w01 = 0.f;
        if (!(vy1 && vx0)) w10 = 0.f;
        if (!(vy1 && vx1)) w11 = 0.f;
        const int cy0 = min(max(y0, 0), 63), cy1 = min(max(y0 + 1, 0), 63);
        const int cx0 = min(max(x0, 0), 63), cx1 = min(max(x0 + 1, 0), 63);
        const int o00 = (cy0 * 64 + cx0) << 10, o01 = (cy0 * 64 + cx1) << 10;
        const int o10 = (cy1 * 64 + cx0) << 10, o11 = (cy1 * 64 + cx1) << 10;

        #pragma unroll
        for (int j = 0; j < 8; ++j) {
            const int co = j * 128 + sub * 16;
            const float4 a0 = *(const float4*)(xTb + o00 + co);
            const float4 a1 = *(const float4*)(xTb + o01 + co);
            const float4 a2 = *(const float4*)(xTb + o10 + co);
            const float4 a3 = *(const float4*)(xTb + o11 + co);
            float4 v;
            v.x = w00*a0.x + w01*a1.x + w10*a2.x + w11*a3.x;
            v.y = w00*a0.y + w01*a1.y + w10*a2.y + w11*a3.y;
            v.z = w00*a0.z + w01*a1.z + w10*a2.z + w11*a3.z;
            v.w = w00*a0.w + w01*a1.w + w10*a2.w + w11*a3.w;
            __half2 h0 = __floats2half2_rn(v.x, v.y);
            __half2 h1 = __floats2half2_rn(v.z, v.w);
            const int ko = tap * 256 + j * 32 + sub * 4;
            *(uint2*)(dA + ko) = make_uint2(*(uint32_t*)&h0, *(uint32_t*)&h1);
        }
    }
}

// ---------------- asm helpers ----------------
__device__ __forceinline__ uint32_t smem_u32(const void* p) {
    uint32_t a;
    asm("{ .reg .u64 t; cvta.to.shared.u64 t, %1; cvt.u32.u64 %0, t; }"
        : "=r"(a) : "l"(p));
    return a;
}
__device__ __forceinline__ void ldsm4(uint32_t* r, uint32_t a) {
    asm volatile("ldmatrix.sync.aligned.m8n8.x4.shared.b16 {%0,%1,%2,%3}, [%4];"
                 : "=r"(r[0]), "=r"(r[1]), "=r"(r[2]), "=r"(r[3]) : "r"(a));
}
__device__ __forceinline__ void hmma(float* d, const uint32_t* a,
                                     uint32_t b0, uint32_t b1) {
    asm volatile(
        "mma.sync.aligned.m16n8k16.row.col.f32.f16.f16.f32 "
        "{%0,%1,%2,%3}, {%4,%5,%6,%7}, {%8,%9}, {%0,%1,%2,%3};"
        : "+f"(d[0]), "+f"(d[1]), "+f"(d[2]), "+f"(d[3])
        : "r"(a[0]), "r"(a[1]), "r"(a[2]), "r"(a[3]), "r"(b0), "r"(b1));
}
__device__ __forceinline__ void cpasync16(uint32_t dst, const void* src) {
    asm volatile("cp.async.cg.shared.global [%0], [%1], 16;"
                 :: "r"(dst), "l"(src) : "memory");
}

// ---------------- dense GEMM, 2-term fp16: A*(Bh + Bl) ----------------
__global__ __launch_bounds__(NTHREADS, 1)
void gemm(const float* __restrict__ bias, float* __restrict__ out)
{
    extern __shared__ char smem[];
    const uint32_t sbase = smem_u32(smem);
    const int tid = threadIdx.x;
    const int wid = tid >> 5;
    const int lid = tid & 31;

    const int mtile = blockIdx.x * BM;
    const int b   = mtile >> 12;
    const int hw0 = mtile & 4095;

    // 8 warps: 2 m-groups x 4 n-groups, warp tile M64 x N64
    const int mrow = (wid & 1) * 64;
    const int ncol = (wid >> 1) * 64;
    const uint32_t aoff = (uint32_t)(lid & 15) * PITCH + (uint32_t)(lid >> 4) * 16;
    const uint32_t boff = (uint32_t)(lid & 7) * PITCH
                        + (uint32_t)((lid >> 3) & 1) * 16
                        + (uint32_t)(lid >> 4) * (8 * PITCH);

    float acc[4][8][4];
    #pragma unroll
    for (int i = 0; i < 4; ++i)
        #pragma unroll
        for (int j = 0; j < 8; ++j)
            #pragma unroll
            for (int k = 0; k < 4; ++k) acc[i][j][k] = 0.f;

    auto fill = [&](int chunk, int st) {
        const int ke = chunk * BK;
        const uint32_t base = sbase + st * STAGE;
        // A: 1024 x 16B -> 4 per thread
        #pragma unroll
        for (int i = 0; i < 4; ++i) {
            const int id = tid + (i << 8);
            const int row = id >> 3, s = id & 7;
            const uint32_t d = (uint32_t)(row * PITCH + s * 16);
            cpasync16(base + GA + d, g_Af + (size_t)(mtile + row) * KTOT + ke + s * 8);
        }
        // B hi/lo: 2048 x 16B each -> 8 per thread per split
        #pragma unroll
        for (int i = 0; i < 8; ++i) {
            const int id = tid + (i << 8);
            const int n = id >> 3, s = id & 7;
            const uint32_t d = (uint32_t)(n * PITCH + s * 16);
            const size_t g = (size_t)n * KTOT + ke + s * 8;
            cpasync16(base + GBH + d, g_wBh + g);
            cpasync16(base + GBL + d, g_wBl + g);
        }
        asm volatile("cp.async.commit_group;" ::: "memory");
    };

    auto do_mma = [&](int st) {
        const uint32_t base = sbase + st * STAGE;
        const uint32_t sA  = base + GA  + mrow * PITCH + aoff;
        const uint32_t sBh = base + GBH + ncol * PITCH + boff;
        const uint32_t sBl = base + GBL + ncol * PITCH + boff;
        #pragma unroll
        for (int ks = 0; ks < 4; ++ks) {
            const uint32_t ka = ks * 32;
            uint32_t a4[4][4];
            #pragma unroll
            for (int ms = 0; ms < 4; ++ms)
                ldsm4(a4[ms], sA + ms * (16 * PITCH) + ka);
            #pragma unroll
            for (int np = 0; np < 4; ++np) {
                uint32_t bh4[4], bl4[4];
                ldsm4(bh4, sBh + np * (16 * PITCH) + ka);
                ldsm4(bl4, sBl + np * (16 * PITCH) + ka);
                #pragma unroll
                for (int ms = 0; ms < 4; ++ms) {
                    hmma(acc[ms][np * 2],     a4[ms], bh4[0], bh4[1]);
                    hmma(acc[ms][np * 2 + 1], a4[ms], bh4[2], bh4[3]);
                    hmma(acc[ms][np * 2],     a4[ms], bl4[0], bl4[1]);
                    hmma(acc[ms][np * 2 + 1], a4[ms], bl4[2], bl4[3]);
                }
            }
        }
    };

    // ---- 2-stage pipeline (fill(i+1) issued before mma(i); wait after) ----
    fill(0, 0);
    asm volatile("cp.async.wait_group 0;" ::: "memory");
    __syncthreads();

    #pragma unroll 1
    for (int chunk = 0; chunk < NCHUNK; ++chunk) {
        const int st = chunk & 1;
        if (chunk + 1 < NCHUNK) fill(chunk + 1, st ^ 1);
        do_mma(st);
        asm volatile("cp.async.wait_group 0;" ::: "memory");
        __syncthreads();
    }

    // ---- epilogue: transpose through smem, coalesced stores ----
    float* csf = (float*)smem;
    const int g  = lid >> 2;
    const int t2 = (lid & 3) * 2;
    const int outbase = (b << 20) + hw0;
    #pragma unroll 1
    for (int p = 0; p < 8; ++p) {
        if ((wid >> 1) == (p >> 1)) {
            const int nsb = (p & 1) * 4;
            #pragma unroll
            for (int ns2 = 0; ns2 < 4; ++ns2) {
                const int nl = ns2 * 8 + t2;
                #pragma unroll
                for (int ms = 0; ms < 4; ++ms) {
                    const float* a4 = acc[ms][nsb + ns2];
                    const int m = mrow + ms * 16 + g;
                    csf[nl * CS_PITCH + m]           = a4[0];
                    csf[(nl + 1) * CS_PITCH + m]     = a4[1];
                    csf[nl * CS_PITCH + m + 8]       = a4[2];
                    csf[(nl + 1) * CS_PITCH + m + 8] = a4[3];
                }
            }
        }
        __syncthreads();
        #pragma unroll
        for (int it = 0; it < 16; ++it) {
            const int e = tid + it * NTHREADS;
            const int mm = e & 127;
            const int nn = e >> 7;          // 0..31
            const int n = p * 32 + nn;
            out[outbase + (n << 12) + mm] = csf[nn * CS_PITCH + mm] + __ldg(bias + n);
        }
        __syncthreads();
    }
}

extern "C" void kernel_launch(void* const* d_in, const int* in_sizes, int n_in,
                              void* d_out, int out_size)
{
    const float* x    = (const float*)d_in[0];
    const float* off  = (const float*)d_in[1];
    const float* w    = (const float*)d_in[2];
    const float* bias = (const float*)d_in[3];
    float* out        = (float*)d_out;

    cudaFuncSetAttribute(gemm, cudaFuncAttributeMaxDynamicSharedMemorySize, GSMEM);

    transpose_x<<<dim3(HW / 32, C_IN / 32, 4), dim3(32, 8)>>>(x);
    prep_w<<<(C_OUT * KTOT) / 256, 256>>>(w);
    im2col_f16<<<MTOT / 32, 256>>>(off);
    gemm<<<MTOT / BM, NTHREADS, GSMEM>>>(bias, out);
}

// round 12
// speedup vs baseline: 2.9511x; 2.5530x over previous
#include <cuda_runtime.h>
#include <cuda_fp16.h>
#include <cstdint>

// ---------------- problem constants ----------------
#define C_IN   256
#define C_OUT  256
#define HW     4096
#define KTAPS  9
#define KTOT   2304          // tap-major: kord = tap*256 + c
#define MTOT   16384

// ---------------- GEMM tiling ----------------
#define BM 128
#define BN 128
#define BK 64
#define NCHUNK 36            // KTOT/BK
#define NTHREADS 256

#define PITCH 144            // 64 k * 2B + 16B pad (conflict-free)
#define ABUF  (BM * PITCH)   // 18432
#define BBUF  (BN * PITCH)   // 18432
#define STAGE (ABUF + 2 * BBUF)       // 55296
#define GA  0
#define GBH ABUF
#define GBL (ABUF + BBUF)
#define GSMEM (2 * STAGE)    // 110592  -> 2 CTAs/SM

#define CS_PITCH 129

// ---------------- device scratch ----------------
__device__ float    g_xT[4 * HW * C_IN];                  // NHWC, 16MB
__device__ __align__(16) uint16_t g_wBh[C_OUT * KTOT];    // fp16 hi, [o][kord]
__device__ __align__(16) uint16_t g_wBl[C_OUT * KTOT];    // fp16 lo (residual)
__device__ __align__(16) uint16_t g_Af[(size_t)MTOT * KTOT];  // im2col fp16

// ---------------- prep kernels ----------------
__global__ void prep_w(const float* __restrict__ w) {
    int i = blockIdx.x * 256 + threadIdx.x;
    int kord = i % KTOT;
    int o    = i / KTOT;
    int tap  = kord >> 8;
    int c    = kord & 255;
    float v = w[o * KTOT + c * KTAPS + tap];
    __half h = __float2half_rn(v);
    float r = v - __half2float(h);
    __half l = __float2half_rn(r);
    g_wBh[i] = *(uint16_t*)&h;
    g_wBl[i] = *(uint16_t*)&l;
}

__global__ void transpose_x(const float* __restrict__ x) {
    __shared__ float t[32][33];
    const int b   = blockIdx.z;
    const int hw0 = blockIdx.x * 32;
    const int c0  = blockIdx.y * 32;
    const int tx  = threadIdx.x, ty = threadIdx.y;
    #pragma unroll
    for (int i = 0; i < 4; ++i)
        t[ty + i * 8][tx] = x[((b * C_IN + c0 + ty + i * 8) << 12) + hw0 + tx];
    __syncthreads();
    #pragma unroll
    for (int i = 0; i < 4; ++i)
        g_xT[b * (HW * C_IN) + (hw0 + ty + i * 8) * C_IN + c0 + tx] =
            t[tx][ty + i * 8];
}

// ---------------- im2col -> single fp16 (no smem, no syncs) ----------------
__global__ __launch_bounds__(256)
void im2col_f16(const float* __restrict__ off)
{
    const int tid = threadIdx.x;
    const int pos = tid >> 3;
    const int sub = tid & 7;
    const int m   = blockIdx.x * 32 + pos;
    const int b   = m >> 12;
    const int hw  = m & 4095;
    const int ho  = hw >> 6, wo = hw & 63;
    const char* xTb = (const char*)g_xT + ((size_t)b << 22);
    uint16_t* dA = g_Af + (size_t)m * KTOT;

    #pragma unroll 1
    for (int tap = 0; tap < KTAPS; ++tap) {
        const float offy = off[((b * 18 + 2 * tap)     << 12) + hw];
        const float offx = off[((b * 18 + 2 * tap + 1) << 12) + hw];
        const float py = (float)(ho - 1 + tap / 3) + offy;
        const float px = (float)(wo - 1 + tap % 3) + offx;
        const float y0f = floorf(py), x0f = floorf(px);
        const int y0 = (int)y0f, x0 = (int)x0f;
        const float fy = py - y0f, fx = px - x0f;
        float w00 = (1.f - fy) * (1.f - fx), w01 = (1.f - fy) * fx;
        float w10 = fy * (1.f - fx),         w11 = fy * fx;
        const bool vy0 = (unsigned)y0 < 64u, vy1 = (unsigned)(y0 + 1) < 64u;
        const bool vx0 = (unsigned)x0 < 64u, vx1 = (unsigned)(x0 + 1) < 64u;
        if (!(vy0 && vx0)) w00 = 0.f;
        if (!(vy0 && vx1)) w01 = 0.f;
        if (!(vy1 && vx0)) w10 = 0.f;
        if (!(vy1 && vx1)) w11 = 0.f;
        const int cy0 = min(max(y0, 0), 63), cy1 = min(max(y0 + 1, 0), 63);
        const int cx0 = min(max(x0, 0), 63), cx1 = min(max(x0 + 1, 0), 63);
        const int o00 = (cy0 * 64 + cx0) << 10, o01 = (cy0 * 64 + cx1) << 10;
        const int o10 = (cy1 * 64 + cx0) << 10, o11 = (cy1 * 64 + cx1) << 10;

        #pragma unroll
        for (int j = 0; j < 8; ++j) {
            const int co = j * 128 + sub * 16;
            const float4 a0 = *(const float4*)(xTb + o00 + co);
            const float4 a1 = *(const float4*)(xTb + o01 + co);
            const float4 a2 = *(const float4*)(xTb + o10 + co);
            const float4 a3 = *(const float4*)(xTb + o11 + co);
            float4 v;
            v.x = w00*a0.x + w01*a1.x + w10*a2.x + w11*a3.x;
            v.y = w00*a0.y + w01*a1.y + w10*a2.y + w11*a3.y;
            v.z = w00*a0.z + w01*a1.z + w10*a2.z + w11*a3.z;
            v.w = w00*a0.w + w01*a1.w + w10*a2.w + w11*a3.w;
            __half2 h0 = __floats2half2_rn(v.x, v.y);
            __half2 h1 = __floats2half2_rn(v.z, v.w);
            const int ko = tap * 256 + j * 32 + sub * 4;
            *(uint2*)(dA + ko) = make_uint2(*(uint32_t*)&h0, *(uint32_t*)&h1);
        }
    }
}

// ---------------- asm helpers ----------------
__device__ __forceinline__ uint32_t smem_u32(const void* p) {
    uint32_t a;
    asm("{ .reg .u64 t; cvta.to.shared.u64 t, %1; cvt.u32.u64 %0, t; }"
        : "=r"(a) : "l"(p));
    return a;
}
__device__ __forceinline__ void ldsm4(uint32_t* r, uint32_t a) {
    asm volatile("ldmatrix.sync.aligned.m8n8.x4.shared.b16 {%0,%1,%2,%3}, [%4];"
                 : "=r"(r[0]), "=r"(r[1]), "=r"(r[2]), "=r"(r[3]) : "r"(a));
}
__device__ __forceinline__ void hmma(float* d, const uint32_t* a,
                                     uint32_t b0, uint32_t b1) {
    asm volatile(
        "mma.sync.aligned.m16n8k16.row.col.f32.f16.f16.f32 "
        "{%0,%1,%2,%3}, {%4,%5,%6,%7}, {%8,%9}, {%0,%1,%2,%3};"
        : "+f"(d[0]), "+f"(d[1]), "+f"(d[2]), "+f"(d[3])
        : "r"(a[0]), "r"(a[1]), "r"(a[2]), "r"(a[3]), "r"(b0), "r"(b1));
}
__device__ __forceinline__ void cpasync16(uint32_t dst, const void* src) {
    asm volatile("cp.async.cg.shared.global [%0], [%1], 16;"
                 :: "r"(dst), "l"(src) : "memory");
}

// ---------------- dense GEMM, 2-term fp16: A*(Bh + Bl), 2 CTAs/SM ----------
__global__ __launch_bounds__(NTHREADS, 2)
void gemm(const float* __restrict__ bias, float* __restrict__ out)
{
    extern __shared__ char smem[];
    const uint32_t sbase = smem_u32(smem);
    const int tid = threadIdx.x;
    const int wid = tid >> 5;
    const int lid = tid & 31;

    const int mtile = blockIdx.x * BM;
    const int ntile = blockIdx.y * BN;
    const int b   = mtile >> 12;
    const int hw0 = mtile & 4095;

    // 8 warps: 2 m-groups x 4 n-groups, warp tile M64 x N32
    const int mrow = (wid & 1) * 64;
    const int ncol = (wid >> 1) * 32;
    const uint32_t aoff = (uint32_t)(lid & 15) * PITCH + (uint32_t)(lid >> 4) * 16;
    const uint32_t boff = (uint32_t)(lid & 7) * PITCH
                        + (uint32_t)((lid >> 3) & 1) * 16
                        + (uint32_t)(lid >> 4) * (8 * PITCH);

    float acc[4][4][4];
    #pragma unroll
    for (int i = 0; i < 4; ++i)
        #pragma unroll
        for (int j = 0; j < 4; ++j)
            #pragma unroll
            for (int k = 0; k < 4; ++k) acc[i][j][k] = 0.f;

    auto fill = [&](int chunk, int st) {
        const int ke = chunk * BK;
        const uint32_t base = sbase + st * STAGE;
        // A + B hi/lo: 128 rows x 8 sixteenB each -> 4 per thread per tensor
        #pragma unroll
        for (int i = 0; i < 4; ++i) {
            const int id = tid + (i << 8);
            const int row = id >> 3, s = id & 7;
            const uint32_t d = (uint32_t)(row * PITCH + s * 16);
            cpasync16(base + GA + d,
                      g_Af + (size_t)(mtile + row) * KTOT + ke + s * 8);
            const size_t gb = (size_t)(ntile + row) * KTOT + ke + s * 8;
            cpasync16(base + GBH + d, g_wBh + gb);
            cpasync16(base + GBL + d, g_wBl + gb);
        }
        asm volatile("cp.async.commit_group;" ::: "memory");
    };

    auto do_mma = [&](int st) {
        const uint32_t base = sbase + st * STAGE;
        const uint32_t sA  = base + GA  + mrow * PITCH + aoff;
        const uint32_t sBh = base + GBH + ncol * PITCH + boff;
        const uint32_t sBl = base + GBL + ncol * PITCH + boff;
        #pragma unroll
        for (int ks = 0; ks < 4; ++ks) {
            const uint32_t ka = ks * 32;
            uint32_t a4[4][4];
            #pragma unroll
            for (int ms = 0; ms < 4; ++ms)
                ldsm4(a4[ms], sA + ms * (16 * PITCH) + ka);
            #pragma unroll
            for (int np = 0; np < 2; ++np) {
                uint32_t bh4[4], bl4[4];
                ldsm4(bh4, sBh + np * (16 * PITCH) + ka);
                ldsm4(bl4, sBl + np * (16 * PITCH) + ka);
                #pragma unroll
                for (int ms = 0; ms < 4; ++ms) {
                    hmma(acc[ms][np * 2],     a4[ms], bh4[0], bh4[1]);
                    hmma(acc[ms][np * 2 + 1], a4[ms], bh4[2], bh4[3]);
                    hmma(acc[ms][np * 2],     a4[ms], bl4[0], bl4[1]);
                    hmma(acc[ms][np * 2 + 1], a4[ms], bl4[2], bl4[3]);
                }
            }
        }
    };

    // ---- 2-stage pipeline ----
    fill(0, 0);
    asm volatile("cp.async.wait_group 0;" ::: "memory");
    __syncthreads();

    #pragma unroll 1
    for (int chunk = 0; chunk < NCHUNK; ++chunk) {
        const int st = chunk & 1;
        if (chunk + 1 < NCHUNK) fill(chunk + 1, st ^ 1);
        do_mma(st);
        asm volatile("cp.async.wait_group 0;" ::: "memory");
        __syncthreads();
    }

    // ---- epilogue: transpose through smem, coalesced stores ----
    float* csf = (float*)smem;
    const int g  = lid >> 2;
    const int t2 = (lid & 3) * 2;
    const int outbase = (b << 20) + hw0;
    #pragma unroll 1
    for (int p = 0; p < 4; ++p) {
        if ((wid >> 1) == p) {
            #pragma unroll
            for (int j = 0; j < 4; ++j) {
                const int nl = j * 8 + t2;
                #pragma unroll
                for (int ms = 0; ms < 4; ++ms) {
                    const float* a4 = acc[ms][j];
                    const int m = mrow + ms * 16 + g;
                    csf[nl * CS_PITCH + m]           = a4[0];
                    csf[(nl + 1) * CS_PITCH + m]     = a4[1];
                    csf[nl * CS_PITCH + m + 8]       = a4[2];
                    csf[(nl + 1) * CS_PITCH + m + 8] = a4[3];
                }
            }
        }
        __syncthreads();
        #pragma unroll
        for (int it = 0; it < 16; ++it) {
            const int e = tid + it * NTHREADS;
            const int mm = e & 127;
            const int nn = e >> 7;          // 0..31
            const int n = ntile + p * 32 + nn;
            out[outbase + (n << 12) + mm] = csf[nn * CS_PITCH + mm] + __ldg(bias + n);
        }
        __syncthreads();
    }
}

extern "C" void kernel_launch(void* const* d_in, const int* in_sizes, int n_in,
                              void* d_out, int out_size)
{
    const float* x    = (const float*)d_in[0];
    const float* off  = (const float*)d_in[1];
    const float* w    = (const float*)d_in[2];
    const float* bias = (const float*)d_in[3];
    float* out        = (float*)d_out;

    cudaFuncSetAttribute(gemm, cudaFuncAttributeMaxDynamicSharedMemorySize, GSMEM);

    transpose_x<<<dim3(HW / 32, C_IN / 32, 4), dim3(32, 8)>>>(x);
    prep_w<<<(C_OUT * KTOT) / 256, 256>>>(w);
    im2col_f16<<<MTOT / 32, 256>>>(off);
    gemm<<<dim3(MTOT / BM, C_OUT / BN), NTHREADS, GSMEM>>>(bias, out);
}